// round 4
// baseline (speedup 1.0000x reference)
#include <cuda_runtime.h>
#include <cuda_bf16.h>
#include <cstdint>

#define BB   512
#define CC   3
#define TT   500
#define DD   40
#define CD   120
#define NN   256
#define OUTN 12
#define BN   (BB*NN)        // 131072
#define SW   (BN/32)        // 4096 bit-words per timestep
#define B_J0 0.01f
#define BETA 1.8f

// ------------------------- device scratch (allocation-guard-safe) -----------
__device__ float    g_i1[(size_t)TT * BB * NN];     // 262 MB (i1, then reused as i2in)
__device__ unsigned g_s1[(size_t)TT * SW];          // 8.2 MB
__device__ float    g_W2inTp[NN * NN];              // [j][n] transposed
__device__ float    g_W2recTp[NN * NN];             // [j][n] transposed
__device__ float    g_acc[BB * OUTN];

// ------------------------- packed f32x2 helpers -----------------------------
__device__ __forceinline__ unsigned long long pack_dup(float a) {
    unsigned long long r;
    asm("mov.b64 %0, {%1,%1};" : "=l"(r) : "f"(a));
    return r;
}
__device__ __forceinline__ void unpack2(unsigned long long v, float& a, float& b) {
    asm("mov.b64 {%0,%1}, %2;" : "=f"(a), "=f"(b) : "l"(v));
}
__device__ __forceinline__ void fma2(unsigned long long& acc,
                                     unsigned long long a, unsigned long long b) {
    asm("fma.rn.f32x2 %0, %1, %2, %0;" : "+l"(acc) : "l"(a), "l"(b));
}

// ------------------------- cluster helpers ----------------------------------
__device__ __forceinline__ unsigned cluster_rank() {
    unsigned r;
    asm("mov.u32 %0, %%cluster_ctarank;" : "=r"(r));
    return r;
}
__device__ __forceinline__ void st_shared_cluster_u32(unsigned laddr, unsigned rank, unsigned v) {
    asm volatile("{\n\t.reg .b32 ra;\n\t"
                 "mapa.shared::cluster.u32 ra, %0, %1;\n\t"
                 "st.shared::cluster.u32 [ra], %2;\n\t}"
                 :: "r"(laddr), "r"(rank), "r"(v) : "memory");
}
__device__ __forceinline__ void cluster_sync_() {
    asm volatile("barrier.cluster.arrive.aligned;" ::: "memory");
    asm volatile("barrier.cluster.wait.aligned;"   ::: "memory");
}

// ------------------------- K0: transpose W2 matrices ------------------------
__global__ void k0_transpose(const float* __restrict__ W2_in,
                             const float* __restrict__ W2_rec)
{
    int j = blockIdx.x;        // presyn 0..255
    int n = threadIdx.x;       // postsyn 0..255
    g_W2inTp [j * NN + n] = W2_in [n * NN + j];
    g_W2recTp[j * NN + n] = W2_rec[n * NN + j];
}

// ------------------------- K1: spikify + i1 GEMM ----------------------------
// grid 4000 blocks x 256 threads. Block: 64 rows (one t, b0..b0+63) x 256 n.
#define K1_SMEM (CD*NN*4 + CD*64*8 + 64*121*4)
__global__ void __launch_bounds__(256, 1)
k1_gemm1(const float* __restrict__ x, const float* __restrict__ thrp,
         const float* __restrict__ W1, const float* __restrict__ b1)
{
    extern __shared__ float sm[];
    float*              w1t   = sm;                                  // [k][n]
    unsigned long long* xs2   = (unsigned long long*)(sm + CD * NN); // [k][r] dup
    float*              stage = (float*)(xs2 + CD * 64);             // [r][121]

    const int tid = threadIdx.x;
    const int p0  = blockIdx.x * 64;
    const int t   = p0 >> 9;
    const int b0  = p0 & 511;
    const float thr = *thrp;

    {
        const int n = tid;
        const float4* wr = (const float4*)(W1 + n * CD);
        #pragma unroll 5
        for (int q = 0; q < 30; q++) {
            float4 v = wr[q];
            int k = q * 4;
            w1t[(k + 0) * NN + n] = v.x;
            w1t[(k + 1) * NN + n] = v.y;
            w1t[(k + 2) * NN + n] = v.z;
            w1t[(k + 3) * NN + n] = v.w;
        }
    }
    for (int i = tid; i < 64 * CD; i += 256) {
        int r  = i / CD;
        int cd = i % CD;
        int c  = cd / DD, d = cd % DD;
        int b  = b0 + r;
        float xv = x[(((size_t)b * CC + c) * TT + t) * DD + d];
        float s  = (xv > thr) ? 1.0f : ((xv < -thr) ? -1.0f : 0.0f);
        stage[r * 121 + cd] = s;
    }
    __syncthreads();
    for (int i = tid; i < CD * 64; i += 256) {
        int cd = i >> 6;
        int r  = i & 63;
        xs2[cd * 64 + r] = pack_dup(stage[r * 121 + cd]);
    }
    __syncthreads();

    const int ng = tid & 31;
    const int rg = tid >> 5;
    unsigned long long acc[32];
    #pragma unroll
    for (int i = 0; i < 32; i++) acc[i] = 0ull;

    #pragma unroll 2
    for (int k = 0; k < CD; k++) {
        const ulonglong2* wp = (const ulonglong2*)(w1t + k * NN + (ng << 3));
        ulonglong2 wA = wp[0];
        ulonglong2 wB = wp[1];
        const ulonglong2* xp = (const ulonglong2*)(xs2 + k * 64 + (rg << 3));
        ulonglong2 x01 = xp[0], x23 = xp[1], x45 = xp[2], x67 = xp[3];
        unsigned long long xd[8] = {x01.x, x01.y, x23.x, x23.y,
                                    x45.x, x45.y, x67.x, x67.y};
        #pragma unroll
        for (int rr = 0; rr < 8; rr++) {
            fma2(acc[rr * 4 + 0], xd[rr], wA.x);
            fma2(acc[rr * 4 + 1], xd[rr], wA.y);
            fma2(acc[rr * 4 + 2], xd[rr], wB.x);
            fma2(acc[rr * 4 + 3], xd[rr], wB.y);
        }
    }

    float4 bq0 = *(const float4*)(b1 + (ng << 3));
    float4 bq1 = *(const float4*)(b1 + (ng << 3) + 4);
    #pragma unroll
    for (int rr = 0; rr < 8; rr++) {
        float o[8];
        #pragma unroll
        for (int np = 0; np < 4; np++)
            unpack2(acc[rr * 4 + np], o[2 * np], o[2 * np + 1]);
        o[0] += bq0.x; o[1] += bq0.y; o[2] += bq0.z; o[3] += bq0.w;
        o[4] += bq1.x; o[5] += bq1.y; o[6] += bq1.z; o[7] += bq1.w;
        size_t base = (size_t)t * BN + (size_t)(b0 + rg * 8 + rr) * NN + (ng << 3);
        *(float4*)&g_i1[base]     = make_float4(o[0], o[1], o[2], o[3]);
        *(float4*)&g_i1[base + 4] = make_float4(o[4], o[5], o[6], o[7]);
    }
}

// ------------------------- K2: layer-1 ALIF scan -> s1 bits -----------------
__global__ void __launch_bounds__(256)
k2_scan1(const float* __restrict__ tau_adp1, const float* __restrict__ tau_m1)
{
    const int gid  = blockIdx.x * 256 + threadIdx.x;
    const int nidx = gid & 255;
    const int lane = threadIdx.x & 31;
    const unsigned wordIdx = gid >> 5;

    const float alpha = __expf(-1.0f / tau_m1[nidx]);
    const float rho   = __expf(-1.0f / tau_adp1[nidx]);
    const float ca = 1.0f - alpha, cr = 1.0f - rho;

    float m = 0.f, a = B_J0, s = 0.f;
    const float* ip = g_i1 + gid;

    for (int t = 0; t < TT; t += 4) {
        float iv[4];
        #pragma unroll
        for (int k = 0; k < 4; k++) iv[k] = ip[(size_t)(t + k) * BN];
        #pragma unroll
        for (int k = 0; k < 4; k++) {
            a = rho * a + cr * s;
            float Bth = B_J0 + BETA * a;
            m = alpha * m + ca * iv[k] - Bth * s;
            s = (m - Bth > 0.f) ? 1.f : 0.f;
            unsigned bal = __ballot_sync(0xffffffffu, s > 0.5f);
            if (lane == 0) g_s1[(size_t)(t + k) * SW + wordIdx] = bal;
        }
    }
}

// ------------------------- K2.5: i2in = b2 + s1 @ W2_in^T (parallel) --------
// grid 1000 CTAs (h = blockIdx&1 selects postsyn half, t = blockIdx>>1).
// CTA holds its 128KB W2in^T half in smem, processes 512 rows (all b of one t).
// Overwrites g_i1 in place (i1 consumed by K2 already).
#define K25_SMEM (NN*128*4 + 16*4)
__global__ void __launch_bounds__(256, 1)
k25_gemm2in(const float* __restrict__ b2_in, const float* __restrict__ b2_rec)
{
    extern __shared__ float sm[];
    float*    w2h    = sm;                         // [j][nl] 256x128
    unsigned* swords = (unsigned*)(sm + NN * 128); // [2][8]

    const int tid  = threadIdx.x;
    const int h    = blockIdx.x & 1;
    const int t    = blockIdx.x >> 1;
    const int nl   = tid & 127;
    const int slot = tid >> 7;

    for (int i = tid; i < NN * 128; i += 256) {
        int j = i >> 7, q = i & 127;
        w2h[i] = g_W2inTp[j * NN + h * 128 + q];
    }
    const float bias = b2_in[h * 128 + nl] + b2_rec[h * 128 + nl];
    __syncthreads();

    const size_t tbase = (size_t)t * BN;
    for (int p = 0; p < 256; p++) {
        if (tid < 16)
            swords[tid] = g_s1[(size_t)t * SW + (size_t)(2 * p + (tid >> 3)) * 8 + (tid & 7)];
        __syncthreads();
        unsigned wv[8];
        #pragma unroll
        for (int w = 0; w < 8; w++) wv[w] = swords[slot * 8 + w];

        float acc = bias;
        #pragma unroll
        for (int w = 0; w < 8; w++) {
            unsigned m = wv[w];
            const float* base = w2h + (w * 32) * 128 + nl;
            while (m) {
                int j = __ffs((int)m) - 1;
                m &= m - 1;
                acc += base[j * 128];
            }
        }
        g_i1[tbase + (size_t)(2 * p + slot) * NN + h * 128 + nl] = acc;
        __syncthreads();
    }
}

// ------------------------- K3: sequential layer-2(rec) + layer-3 ------------
// 64 clusters x 2 CTAs, 256 threads. CTA rank r owns postsyn neurons
// [128r,128r+128) with its W2rec^T slice in smem (128KB). Warp g = batch
// bbase+g; lane owns neurons nl = k*32+lane (k=0..3). Per step: prefetched
// i2in + smem gather of s2 spikes; ballots exchanged via st.shared::cluster;
// one cluster barrier per step. Layer-3 deferred one step, split across ranks.
#define K3G 8
#define K3_SMEM (NN*128*4 + OUTN*257*4 + 128*4)
__global__ void __cluster_dims__(2, 1, 1) __launch_bounds__(256, 1)
k3_recurrent(const float* __restrict__ W3, const float* __restrict__ b3,
             const float* __restrict__ tau_adp2, const float* __restrict__ tau_m2,
             const float* __restrict__ tau_m3)
{
    extern __shared__ float sm[];
    float*    w2s   = sm;                                   // [j][nl] 256x128
    float*    W3s   = sm + NN * 128;                        // [o][257]
    unsigned* words = (unsigned*)(W3s + OUTN * 257);        // [2][8][8]

    const unsigned rank = cluster_rank();
    const int tid   = threadIdx.x;
    const int lane  = tid & 31;
    const int g     = tid >> 5;                 // warp = batch slot
    const int cid   = blockIdx.x >> 1;
    const int b     = cid * K3G + g;

    for (int i = tid; i < NN * 128; i += 256) {
        int j = i >> 7, q = i & 127;
        w2s[i] = g_W2recTp[j * NN + rank * 128 + q];
    }
    for (int i = tid; i < OUTN * NN; i += 256)
        W3s[(i >> 8) * 257 + (i & 255)] = W3[i];
    if (tid < 128) words[tid] = 0u;

    // per-thread layer-2 state: neurons n_k = rank*128 + k*32 + lane
    float al2[4], rh2[4], m2[4], a2[4], s2[4];
    #pragma unroll
    for (int k = 0; k < 4; k++) {
        int n = rank * 128 + k * 32 + lane;
        al2[k] = __expf(-1.0f / tau_m2[n]);
        rh2[k] = __expf(-1.0f / tau_adp2[n]);
        m2[k] = 0.f; a2[k] = B_J0; s2[k] = 0.f;
    }
    // layer-3 state: rank handles outputs o = rank*6 + lane (lane<6)
    const int o3 = rank * 6 + lane;
    float al3 = 1.f, m3 = 0.f, accr = 0.f, b3v = 0.f;
    if (lane < 6) { al3 = __expf(-1.0f / tau_m3[o3]); b3v = b3[o3]; }

    const unsigned words_base = (unsigned)__cvta_generic_to_shared(words);

    __syncthreads();
    cluster_sync_();

    const float* i2p = g_i1 + (size_t)b * NN + rank * 128 + lane;
    float iv[4];
    #pragma unroll
    for (int k = 0; k < 4; k++) iv[k] = i2p[k * 32];     // t = 0

    for (int t = 0; t < TT; t++) {
        const int cur = t & 1, nxt = cur ^ 1;

        // prefetch next step's i2in
        float nv[4];
        {
            int tn = (t + 1 < TT) ? (t + 1) : t;
            #pragma unroll
            for (int k = 0; k < 4; k++) nv[k] = i2p[(size_t)tn * BN + k * 32];
        }

        // deferred layer-3 for step t-1, split across ranks (uses words[cur] = s2(t-1))
        if (lane < 6 && t > 0) {
            float i3 = b3v;
            const float* wr = &W3s[o3 * 257];
            #pragma unroll
            for (int w = 0; w < 8; w++) {
                unsigned m = words[(cur * 8 + g) * 8 + w];
                int basej = ((w >> 2) * 128) + ((w & 3) * 32);
                while (m) {
                    int j = __ffs((int)m) - 1;
                    m &= m - 1;
                    i3 += wr[basej + j];
                }
            }
            m3 = al3 * m3 + (1.0f - al3) * i3;
            accr += m3;
        }

        // recurrent gather from smem
        float i2[4] = { iv[0], iv[1], iv[2], iv[3] };
        #pragma unroll
        for (int w = 0; w < 8; w++) {
            unsigned m = words[(cur * 8 + g) * 8 + w];
            int basej = ((w >> 2) * 128) + ((w & 3) * 32);
            const float* wb = w2s + basej * 128 + lane;
            while (m) {
                int j = __ffs((int)m) - 1;
                m &= m - 1;
                const float* r = wb + j * 128;
                i2[0] += r[0];
                i2[1] += r[32];
                i2[2] += r[64];
                i2[3] += r[96];
            }
        }

        // ALIF update
        unsigned bal[4];
        #pragma unroll
        for (int k = 0; k < 4; k++) {
            a2[k] = rh2[k] * a2[k] + (1.0f - rh2[k]) * s2[k];
            float Bth = B_J0 + BETA * a2[k];
            m2[k] = al2[k] * m2[k] + (1.0f - al2[k]) * i2[k] - Bth * s2[k];
            s2[k] = (m2[k] - Bth > 0.f) ? 1.f : 0.f;
            bal[k] = __ballot_sync(0xffffffffu, s2[k] > 0.5f);
        }

        // publish ballots to both CTAs: word index rank*4+k
        if (lane < 4) {
            unsigned v = bal[lane];
            unsigned off = (((unsigned)nxt * 8 + (unsigned)g) * 8 + rank * 4 + (unsigned)lane) * 4;
            words[((nxt * 8 + g) * 8) + rank * 4 + lane] = v;          // local
            st_shared_cluster_u32(words_base + off, rank ^ 1u, v);     // peer
        }
        cluster_sync_();

        #pragma unroll
        for (int k = 0; k < 4; k++) iv[k] = nv[k];
    }

    // final deferred layer-3 (step TT-1; cur would be TT&1 = 0)
    if (lane < 6) {
        float i3 = b3v;
        const float* wr = &W3s[o3 * 257];
        #pragma unroll
        for (int w = 0; w < 8; w++) {
            unsigned m = words[(0 * 8 + g) * 8 + w];
            int basej = ((w >> 2) * 128) + ((w & 3) * 32);
            while (m) {
                int j = __ffs((int)m) - 1;
                m &= m - 1;
                i3 += wr[basej + j];
            }
        }
        m3 = al3 * m3 + (1.0f - al3) * i3;
        accr += m3;
        g_acc[b * OUTN + o3] = accr;
    }
}

// ------------------------- K4: log-softmax ----------------------------------
__global__ void __launch_bounds__(256)
k4_softmax(float* __restrict__ out)
{
    int b = blockIdx.x * 256 + threadIdx.x;
    if (b >= BB) return;
    float v[OUTN];
    float mx = -1e30f;
    #pragma unroll
    for (int o = 0; o < OUTN; o++) {
        v[o] = g_acc[b * OUTN + o] * (1.0f / (float)TT);
        mx = fmaxf(mx, v[o]);
    }
    float sum = 0.f;
    #pragma unroll
    for (int o = 0; o < OUTN; o++) sum += __expf(v[o] - mx);
    float lse = mx + __logf(sum);
    #pragma unroll
    for (int o = 0; o < OUTN; o++) out[b * OUTN + o] = v[o] - lse;
}

// ------------------------- launch -------------------------------------------
extern "C" void kernel_launch(void* const* d_in, const int* in_sizes, int n_in,
                              void* d_out, int out_size)
{
    const float* x        = (const float*)d_in[0];
    const float* thr      = (const float*)d_in[1];
    const float* W1       = (const float*)d_in[2];
    const float* b1       = (const float*)d_in[3];
    const float* W2_in    = (const float*)d_in[4];
    const float* b2_in    = (const float*)d_in[5];
    const float* W2_rec   = (const float*)d_in[6];
    const float* b2_rec   = (const float*)d_in[7];
    const float* W3       = (const float*)d_in[8];
    const float* b3       = (const float*)d_in[9];
    const float* tau_adp1 = (const float*)d_in[10];
    const float* tau_m1   = (const float*)d_in[11];
    const float* tau_adp2 = (const float*)d_in[12];
    const float* tau_m2   = (const float*)d_in[13];
    const float* tau_m3   = (const float*)d_in[14];
    float* out = (float*)d_out;

    cudaFuncSetAttribute(k1_gemm1,    cudaFuncAttributeMaxDynamicSharedMemorySize, K1_SMEM);
    cudaFuncSetAttribute(k25_gemm2in, cudaFuncAttributeMaxDynamicSharedMemorySize, K25_SMEM);
    cudaFuncSetAttribute(k3_recurrent, cudaFuncAttributeMaxDynamicSharedMemorySize, K3_SMEM);

    k0_transpose<<<NN, NN>>>(W2_in, W2_rec);
    k1_gemm1<<<(TT * BB) / 64, 256, K1_SMEM>>>(x, thr, W1, b1);
    k2_scan1<<<BB, 256>>>(tau_adp1, tau_m1);
    k25_gemm2in<<<2 * TT, 256, K25_SMEM>>>(b2_in, b2_rec);
    k3_recurrent<<<128, 256, K3_SMEM>>>(W3, b3, tau_adp2, tau_m2, tau_m3);
    k4_softmax<<<(BB + 255) / 256, 256>>>(out);
}